// round 15
// baseline (speedup 1.0000x reference)
#include <cuda_runtime.h>
#include <cuda_bf16.h>
#include <cstdint>

// Problem constants: N=50000 nodes, E=800000 edges, D=C=128, H=1
#define NMAX 50000
#define EMAX 800000
#define EE   (EMAX + NMAX)
constexpr int DDIM = 128;
constexpr int SCAN_FLAG = 1 << 30;
constexpr int GEMM_GRID = 148;     // persistent: one CTA per SM

// bf16 tile layout: 136 bf16 per row (pad) = 68 32-bit words; bank = 4*gid+tig
constexpr int RW = 68;             // words per row
constexpr int IMG_W = 128 * RW;    // 8704 words per 128-row bf16 image
constexpr int IMG_F4 = IMG_W / 4;  // 2176 float4 per image

// ---------------- static device scratch ----------------
__device__ float g_xl[(size_t)NMAX * 128];
__device__ float g_h [(size_t)NMAX * 128];
__device__ float g_as[NMAX];
__device__ float g_ad[NMAX];
__device__ int   g_deg[NMAX];
__device__ int   g_rowptr[NMAX + 1];
__device__ int   g_cursor[NMAX];
__device__ int   g_csrsrc[EE];
__device__ int   g_csrdst[EE];
__device__ float g_w[EE];
__device__ int   g_bsum[256];
// W per layer, TRANSPOSED [n][k], bf16 hi/lo, padded rows (136 bf16)
__device__ __align__(16) __nv_bfloat16 g_wbh[2][128 * 136];
__device__ __align__(16) __nv_bfloat16 g_wbl[2][128 * 136];

// ---------------- helpers ----------------
__device__ __forceinline__ void cvt_hi_lo(float a, float b, uint32_t& hi, uint32_t& lo) {
    __nv_bfloat16 ha = __float2bfloat16_rn(a), hb = __float2bfloat16_rn(b);
    float ra = a - __bfloat162float(ha), rb = b - __bfloat162float(hb);
    __nv_bfloat16 la = __float2bfloat16_rn(ra), lb = __float2bfloat16_rn(rb);
    hi = ((uint32_t)(*(unsigned short*)&hb) << 16) | (*(unsigned short*)&ha);
    lo = ((uint32_t)(*(unsigned short*)&lb) << 16) | (*(unsigned short*)&la);
}
__device__ __forceinline__ void mma_bf16(float c[4], const uint32_t a[4], uint32_t b0, uint32_t b1) {
    asm volatile(
        "mma.sync.aligned.m16n8k16.row.col.f32.bf16.bf16.f32 "
        "{%0,%1,%2,%3}, {%4,%5,%6,%7}, {%8,%9}, {%0,%1,%2,%3};"
        : "+f"(c[0]), "+f"(c[1]), "+f"(c[2]), "+f"(c[3])
        : "r"(a[0]), "r"(a[1]), "r"(a[2]), "r"(a[3]), "r"(b0), "r"(b1));
}

// ============================================================================
// Fused prep: blocks [0,128) build W^T bf16 hi/lo images; blocks [128,128+nb)
// init g_deg = 1 (self loop pre-counted); block 128 zeroes scan state.
// ============================================================================
__global__ void prep_kernel(const float* __restrict__ W1, const float* __restrict__ W2, int n) {
    int b = blockIdx.x, t = threadIdx.x;
    if (b < 128) {
        int idx = b * 256 + t;                 // 0..32767
        int layer = idx >> 14;
        int e = idx & 16383;
        int nn = e >> 7, k = e & 127;          // write coalesced in k
        float v = (layer ? W2 : W1)[k * 128 + nn];
        __nv_bfloat16 h = __float2bfloat16_rn(v);
        float r = v - __bfloat162float(h);
        g_wbh[layer][nn * 136 + k] = h;
        g_wbl[layer][nn * 136 + k] = __float2bfloat16_rn(r);
    } else {
        int i = (b - 128) * 256 + t;
        if (i < n) g_deg[i] = 1;               // self loop
        if (b == 128) g_bsum[t] = 0;
    }
}

// ============================================================================
// CSR build
// ============================================================================
__global__ void count_deg_kernel(const int* __restrict__ ei, int E) {
    int i = blockIdx.x * blockDim.x + threadIdx.x;
    if (i < E) atomicAdd(&g_deg[ei[E + i]], 1);
}

__global__ void scan_rowptr_kernel(int n) {
    __shared__ int sh[256];
    __shared__ int red[256];
    int t = threadIdx.x, b = blockIdx.x;
    int i = b * 256 + t;
    int v = (i < n) ? g_deg[i] : 0;
    sh[t] = v;
    __syncthreads();
    for (int o = 1; o < 256; o <<= 1) {
        int u = (t >= o) ? sh[t - o] : 0;
        __syncthreads();
        sh[t] += u;
        __syncthreads();
    }
    if (t == 255) atomicExch(&g_bsum[b], sh[255] + SCAN_FLAG);
    int agg = 0;
    for (int p = t; p < b; p += 256) {
        int val;
        do { val = *(volatile int*)&g_bsum[p]; } while (val < SCAN_FLAG);
        agg += val - SCAN_FLAG;
    }
    red[t] = agg;
    __syncthreads();
    for (int o = 128; o; o >>= 1) {
        if (t < o) red[t] += red[t + o];
        __syncthreads();
    }
    int excl = red[0] + sh[t] - v;
    if (i < n) {
        g_rowptr[i] = excl;
        g_cursor[i] = excl;
        if (i == n - 1) g_rowptr[n] = excl + v;
    }
}

__global__ void scatter_edges_kernel(const int* __restrict__ ei, int E, int n) {
    int i = blockIdx.x * blockDim.x + threadIdx.x;
    if (i < E) {
        int s = ei[i];
        int d = ei[E + i];
        int p = atomicAdd(&g_cursor[d], 1);
        g_csrsrc[p] = s;
        g_csrdst[p] = d;
    } else if (i < E + n) {
        int v = i - E;
        int p = atomicAdd(&g_cursor[v], 1);
        g_csrsrc[p] = v;
        g_csrdst[p] = v;
    }
}

// ============================================================================
// PERSISTENT bf16-split GEMM + attention, SOFTWARE-PIPELINED (unchanged r14).
// ============================================================================
constexpr uint32_t SMEM_WORDS = 6 * IMG_W + 1024;    // X0h|X0l|X1h|X1l|Bh|Bl + staging
constexpr uint32_t SMEM_BYTES = SMEM_WORDS * 4;      // 212992

__global__ __launch_bounds__(512) void gemm_mma_kernel(
    const float* __restrict__ X,
    const float4* __restrict__ Wbh_g, const float4* __restrict__ Wbl_g,
    const float* __restrict__ atts, const float* __restrict__ attd,
    float* __restrict__ XL, int n)
{
    extern __shared__ uint32_t smu[];
    uint32_t* Xb[2][2];
    Xb[0][0] = smu;
    Xb[0][1] = smu + IMG_W;
    Xb[1][0] = smu + 2 * IMG_W;
    Xb[1][1] = smu + 3 * IMG_W;
    uint32_t* Bh = smu + 4 * IMG_W;
    uint32_t* Bl = smu + 5 * IMG_W;
    float* sh_s = (float*)(smu + 6 * IMG_W);
    float* sh_d = sh_s + 512;

    int tid = threadIdx.x, lane = tid & 31, warp = tid >> 5;
    int gid = lane >> 2, tig = lane & 3;
    int nquad = warp >> 2;
    int rbase = (warp & 3) * 32;

    {
        float4* dh = (float4*)Bh;
        float4* dl = (float4*)Bl;
#pragma unroll
        for (int i = 0; i < 5; i++) {
            int idx = tid + i * 512;
            if (idx < IMG_F4) { dh[idx] = Wbh_g[idx]; dl[idx] = Wbl_g[idx]; }
        }
    }

    float avs[4][2], avd[4][2];
#pragma unroll
    for (int nt = 0; nt < 4; nt++) {
        int col = nquad * 32 + nt * 8 + tig * 2;
        avs[nt][0] = __ldg(atts + col); avs[nt][1] = __ldg(atts + col + 1);
        avd[nt][0] = __ldg(attd + col); avd[nt][1] = __ldg(attd + col + 1);
    }

    const float4* X4 = (const float4*)X;
    int ntiles = (n + 127) >> 7;
    int lr[8], lc[8];
#pragma unroll
    for (int j = 0; j < 8; j++) {
        int idx = tid + j * 512;
        lr[j] = idx >> 5; lc[j] = idx & 31;
    }

    {
        int row0 = blockIdx.x << 7;
#pragma unroll
        for (int j = 0; j < 8; j++) {
            float4 v = make_float4(0.f, 0.f, 0.f, 0.f);
            if (row0 + lr[j] < n) v = X4[(size_t)(row0 + lr[j]) * 32 + lc[j]];
            uint32_t h0, l0, h1, l1;
            cvt_hi_lo(v.x, v.y, h0, l0);
            cvt_hi_lo(v.z, v.w, h1, l1);
            int w = lr[j] * RW + lc[j] * 2;
            *(uint2*)(Xb[0][0] + w) = make_uint2(h0, h1);
            *(uint2*)(Xb[0][1] + w) = make_uint2(l0, l1);
        }
    }
    __syncthreads();

    int buf = 0;
    for (int tile = blockIdx.x; tile < ntiles; tile += gridDim.x, buf ^= 1) {
        int row0 = tile << 7;
        uint32_t* Xh = Xb[buf][0];
        uint32_t* Xl = Xb[buf][1];
        uint32_t* Yh = Xb[buf ^ 1][0];
        uint32_t* Yl = Xb[buf ^ 1][1];
        int nrow0 = (tile + gridDim.x) << 7;
        bool have_next = (tile + gridDim.x) < ntiles;

        float c[2][4][4];
#pragma unroll
        for (int g = 0; g < 2; g++)
#pragma unroll
            for (int nt = 0; nt < 4; nt++)
                c[g][nt][0] = c[g][nt][1] = c[g][nt][2] = c[g][nt][3] = 0.f;

        int aro = (rbase + gid) * RW + tig;
        int bro = (nquad * 32 + gid) * RW + tig;

        float4 pv[4];
        if (have_next) {
#pragma unroll
            for (int j = 0; j < 4; j++) {
                pv[j] = make_float4(0.f, 0.f, 0.f, 0.f);
                if (nrow0 + lr[j] < n) pv[j] = X4[(size_t)(nrow0 + lr[j]) * 32 + lc[j]];
            }
        }
#pragma unroll
        for (int ks = 0; ks < 4; ks++) {
            int kw = ks * 8;
            uint32_t ah[2][4], al[2][4];
#pragma unroll
            for (int g = 0; g < 2; g++) {
                int o = aro + g * (16 * RW) + kw;
                ah[g][0] = Xh[o];              al[g][0] = Xl[o];
                ah[g][1] = Xh[o + 8 * RW];     al[g][1] = Xl[o + 8 * RW];
                ah[g][2] = Xh[o + 4];          al[g][2] = Xl[o + 4];
                ah[g][3] = Xh[o + 8 * RW + 4]; al[g][3] = Xl[o + 8 * RW + 4];
            }
#pragma unroll
            for (int nt = 0; nt < 4; nt++) {
                int o = bro + nt * (8 * RW) + kw;
                uint32_t bh0 = Bh[o], bh1 = Bh[o + 4];
                uint32_t bl0 = Bl[o], bl1 = Bl[o + 4];
                mma_bf16(c[0][nt], ah[0], bh0, bh1);
                mma_bf16(c[0][nt], ah[0], bl0, bl1);
                mma_bf16(c[0][nt], al[0], bh0, bh1);
                mma_bf16(c[1][nt], ah[1], bh0, bh1);
                mma_bf16(c[1][nt], ah[1], bl0, bl1);
                mma_bf16(c[1][nt], al[1], bh0, bh1);
            }
        }
        if (have_next) {
#pragma unroll
            for (int j = 0; j < 4; j++) {
                uint32_t h0, l0, h1, l1;
                cvt_hi_lo(pv[j].x, pv[j].y, h0, l0);
                cvt_hi_lo(pv[j].z, pv[j].w, h1, l1);
                int w = lr[j] * RW + lc[j] * 2;
                *(uint2*)(Yh + w) = make_uint2(h0, h1);
                *(uint2*)(Yl + w) = make_uint2(l0, l1);
            }
#pragma unroll
            for (int j = 0; j < 4; j++) {
                pv[j] = make_float4(0.f, 0.f, 0.f, 0.f);
                if (nrow0 + lr[j + 4] < n) pv[j] = X4[(size_t)(nrow0 + lr[j + 4]) * 32 + lc[j + 4]];
            }
        }
#pragma unroll
        for (int ks = 4; ks < 8; ks++) {
            int kw = ks * 8;
            uint32_t ah[2][4], al[2][4];
#pragma unroll
            for (int g = 0; g < 2; g++) {
                int o = aro + g * (16 * RW) + kw;
                ah[g][0] = Xh[o];              al[g][0] = Xl[o];
                ah[g][1] = Xh[o + 8 * RW];     al[g][1] = Xl[o + 8 * RW];
                ah[g][2] = Xh[o + 4];          al[g][2] = Xl[o + 4];
                ah[g][3] = Xh[o + 8 * RW + 4]; al[g][3] = Xl[o + 8 * RW + 4];
            }
#pragma unroll
            for (int nt = 0; nt < 4; nt++) {
                int o = bro + nt * (8 * RW) + kw;
                uint32_t bh0 = Bh[o], bh1 = Bh[o + 4];
                uint32_t bl0 = Bl[o], bl1 = Bl[o + 4];
                mma_bf16(c[0][nt], ah[0], bh0, bh1);
                mma_bf16(c[0][nt], ah[0], bl0, bl1);
                mma_bf16(c[0][nt], al[0], bh0, bh1);
                mma_bf16(c[1][nt], ah[1], bh0, bh1);
                mma_bf16(c[1][nt], ah[1], bl0, bl1);
                mma_bf16(c[1][nt], al[1], bh0, bh1);
            }
        }
        if (have_next) {
#pragma unroll
            for (int j = 0; j < 4; j++) {
                uint32_t h0, l0, h1, l1;
                cvt_hi_lo(pv[j].x, pv[j].y, h0, l0);
                cvt_hi_lo(pv[j].z, pv[j].w, h1, l1);
                int w = lr[j + 4] * RW + lc[j + 4] * 2;
                *(uint2*)(Yh + w) = make_uint2(h0, h1);
                *(uint2*)(Yl + w) = make_uint2(l0, l1);
            }
        }

#pragma unroll
        for (int g = 0; g < 2; g++) {
            float ps0 = 0.f, pd0 = 0.f, ps1 = 0.f, pd1 = 0.f;
#pragma unroll
            for (int nt = 0; nt < 4; nt++) {
                ps0 = fmaf(c[g][nt][0], avs[nt][0], fmaf(c[g][nt][1], avs[nt][1], ps0));
                pd0 = fmaf(c[g][nt][0], avd[nt][0], fmaf(c[g][nt][1], avd[nt][1], pd0));
                ps1 = fmaf(c[g][nt][2], avs[nt][0], fmaf(c[g][nt][3], avs[nt][1], ps1));
                pd1 = fmaf(c[g][nt][2], avd[nt][0], fmaf(c[g][nt][3], avd[nt][1], pd1));
            }
#pragma unroll
            for (int o = 1; o <= 2; o <<= 1) {
                ps0 += __shfl_xor_sync(0xffffffffu, ps0, o);
                pd0 += __shfl_xor_sync(0xffffffffu, pd0, o);
                ps1 += __shfl_xor_sync(0xffffffffu, ps1, o);
                pd1 += __shfl_xor_sync(0xffffffffu, pd1, o);
            }
            int rloc = rbase + g * 16 + gid;
            if (tig == 0) {
                sh_s[nquad * 128 + rloc]     = ps0;
                sh_d[nquad * 128 + rloc]     = pd0;
                sh_s[nquad * 128 + rloc + 8] = ps1;
                sh_d[nquad * 128 + rloc + 8] = pd1;
            }
            int r0 = row0 + rloc;
            int r1 = r0 + 8;
            if (r0 < n) {
                float* dst = XL + (size_t)r0 * 128 + nquad * 32 + tig * 2;
#pragma unroll
                for (int nt = 0; nt < 4; nt++)
                    *(float2*)(dst + nt * 8) = make_float2(c[g][nt][0], c[g][nt][1]);
            }
            if (r1 < n) {
                float* dst = XL + (size_t)r1 * 128 + nquad * 32 + tig * 2;
#pragma unroll
                for (int nt = 0; nt < 4; nt++)
                    *(float2*)(dst + nt * 8) = make_float2(c[g][nt][2], c[g][nt][3]);
            }
        }

        __syncthreads();
        if (tid < 128) {
            int r = row0 + tid;
            if (r < n) {
                g_as[r] = (sh_s[tid] + sh_s[128 + tid]) + (sh_s[256 + tid] + sh_s[384 + tid]);
                g_ad[r] = (sh_d[tid] + sh_d[128 + tid]) + (sh_d[256 + tid] + sh_d[384 + tid]);
            }
        }
    }
}

// ============================================================================
// Per-edge softmax weights (CSR order): w = exp(leakyrelu(a_s[src] + a_d[dst]))
// Fully parallel — removes the dependent src->a_s->exp chain from the
// aggregate's critical loop.
// ============================================================================
__global__ void edge_w_kernel(int ee) {
    int i = blockIdx.x * blockDim.x + threadIdx.x;
    if (i >= ee) return;
    float t = g_as[g_csrsrc[i]] + g_ad[g_csrdst[i]];
    t = t > 0.f ? t : 0.2f * t;
    g_w[i] = __expf(t);
}

// ============================================================================
// Aggregation: one warp per dst node; precomputed w; 8 gathers in flight.
//   out[v] = relu( (sum_e w_e * XL[src_e]) / (sum_e w_e + 1e-16) + b )
// ============================================================================
__global__ __launch_bounds__(256) void aggregate_kernel(
    const float* __restrict__ XL, const float* __restrict__ bias,
    float* __restrict__ OUT, int n)
{
    int wid = blockIdx.x * 8 + (threadIdx.x >> 5);
    int lane = threadIdx.x & 31;
    if (wid >= n) return;

    int beg = g_rowptr[wid];
    int end = g_rowptr[wid + 1];
    float4 acc = make_float4(0.f, 0.f, 0.f, 0.f);
    float z = 0.f;
    const float4* XL4 = (const float4*)XL;

    int j = beg;
    for (; j + 8 <= end; j += 8) {
        int s[8]; float w[8]; float4 x[8];
#pragma unroll
        for (int q = 0; q < 8; q++) { s[q] = g_csrsrc[j + q]; w[q] = g_w[j + q]; }
#pragma unroll
        for (int q = 0; q < 8; q++) x[q] = XL4[(size_t)s[q] * 32 + lane];
#pragma unroll
        for (int q = 0; q < 8; q++) {
            acc.x = fmaf(w[q], x[q].x, acc.x); acc.y = fmaf(w[q], x[q].y, acc.y);
            acc.z = fmaf(w[q], x[q].z, acc.z); acc.w = fmaf(w[q], x[q].w, acc.w);
            z += w[q];
        }
    }
    for (; j + 4 <= end; j += 4) {
        int s[4]; float w[4]; float4 x[4];
#pragma unroll
        for (int q = 0; q < 4; q++) { s[q] = g_csrsrc[j + q]; w[q] = g_w[j + q]; }
#pragma unroll
        for (int q = 0; q < 4; q++) x[q] = XL4[(size_t)s[q] * 32 + lane];
#pragma unroll
        for (int q = 0; q < 4; q++) {
            acc.x = fmaf(w[q], x[q].x, acc.x); acc.y = fmaf(w[q], x[q].y, acc.y);
            acc.z = fmaf(w[q], x[q].z, acc.z); acc.w = fmaf(w[q], x[q].w, acc.w);
            z += w[q];
        }
    }
    for (; j < end; j++) {
        int s = g_csrsrc[j];
        float w = g_w[j];
        float4 xv = XL4[(size_t)s * 32 + lane];
        acc.x = fmaf(w, xv.x, acc.x); acc.y = fmaf(w, xv.y, acc.y);
        acc.z = fmaf(w, xv.z, acc.z); acc.w = fmaf(w, xv.w, acc.w);
        z += w;
    }

    float inv = 1.f / (z + 1e-16f);
    float4 bv = ((const float4*)bias)[lane];
    float4 o;
    o.x = fmaxf(fmaf(acc.x, inv, bv.x), 0.f);
    o.y = fmaxf(fmaf(acc.y, inv, bv.y), 0.f);
    o.z = fmaxf(fmaf(acc.z, inv, bv.z), 0.f);
    o.w = fmaxf(fmaf(acc.w, inv, bv.w), 0.f);
    ((float4*)OUT)[(size_t)wid * 32 + lane] = o;
}

// ============================================================================
// Launch (10 kernels). gemm1 kept at slot 4 (the profiled slot).
// ============================================================================
extern "C" void kernel_launch(void* const* d_in, const int* in_sizes, int n_in,
                              void* d_out, int out_size)
{
    const float* x   = (const float*)d_in[0];
    const int*   ei  = (const int*)d_in[1];
    const float* W1  = (const float*)d_in[2];
    const float* as1 = (const float*)d_in[3];
    const float* ad1 = (const float*)d_in[4];
    const float* b1  = (const float*)d_in[5];
    const float* W2  = (const float*)d_in[6];
    const float* as2 = (const float*)d_in[7];
    const float* ad2 = (const float*)d_in[8];
    const float* b2  = (const float*)d_in[9];

    int n = in_sizes[0] / DDIM;   // 50000
    int E = in_sizes[1] / 2;      // 800000
    int ee = E + n;
    float* out = (float*)d_out;

    void *xl_p, *h_p, *wh_p, *wl_p;
    cudaGetSymbolAddress(&xl_p, g_xl);
    cudaGetSymbolAddress(&h_p,  g_h);
    cudaGetSymbolAddress(&wh_p, g_wbh);
    cudaGetSymbolAddress(&wl_p, g_wbl);
    float* xl = (float*)xl_p;
    float* h  = (float*)h_p;
    const __nv_bfloat16* wbh = (const __nv_bfloat16*)wh_p;
    const __nv_bfloat16* wbl = (const __nv_bfloat16*)wl_p;

    cudaFuncSetAttribute(gemm_mma_kernel, cudaFuncAttributeMaxDynamicSharedMemorySize, SMEM_BYTES);

    int nb = (n + 255) / 256;     // 196

    // --- prep & CSR build (gemm1 at slot 4 for profiling) ---
    prep_kernel<<<128 + nb, 256>>>(W1, W2, n);
    count_deg_kernel<<<(E + 255) / 256, 256>>>(ei, E);
    scan_rowptr_kernel<<<nb, 256>>>(n);
    gemm_mma_kernel<<<GEMM_GRID, 512, SMEM_BYTES>>>(
        x, (const float4*)wbh, (const float4*)wbl, as1, ad1, xl, n);
    scatter_edges_kernel<<<(ee + 255) / 256, 256>>>(ei, E, n);

    // --- Layer 1 ---
    edge_w_kernel<<<(ee + 255) / 256, 256>>>(ee);
    aggregate_kernel<<<(n + 7) / 8, 256>>>(xl, b1, h, n);

    // --- Layer 2 ---
    gemm_mma_kernel<<<GEMM_GRID, 512, SMEM_BYTES>>>(
        h, (const float4*)(wbh + 128 * 136), (const float4*)(wbl + 128 * 136),
        as2, ad2, xl, n);
    edge_w_kernel<<<(ee + 255) / 256, 256>>>(ee);
    aggregate_kernel<<<(n + 7) / 8, 256>>>(xl, b2, out, n);
}

// round 16
// speedup vs baseline: 1.0838x; 1.0838x over previous
#include <cuda_runtime.h>
#include <cuda_bf16.h>
#include <cstdint>

// Problem constants: N=50000 nodes, E=800000 edges, D=C=128, H=1
#define NMAX 50000
#define EMAX 800000
#define EE   (EMAX + NMAX)
constexpr int DDIM = 128;
constexpr int SCAN_FLAG = 1 << 30;
constexpr int GEMM_GRID = 148;     // persistent: one CTA per SM

// bf16 tile layout: 136 bf16 per row (pad) = 68 32-bit words; bank = 4*gid+tig
constexpr int RW = 68;             // words per row
constexpr int IMG_W = 128 * RW;    // 8704 words per 128-row bf16 image
constexpr int IMG_F4 = IMG_W / 4;  // 2176 float4 per image

// ---------------- static device scratch ----------------
__device__ float g_xl[(size_t)NMAX * 128];
__device__ float g_h [(size_t)NMAX * 128];
__device__ float g_as[NMAX];
__device__ float g_ad[NMAX];
__device__ int   g_deg[NMAX];
__device__ int   g_rowptr[NMAX + 1];
__device__ int   g_cursor[NMAX];
__device__ __align__(16) int g_csrsrc[EE];
__device__ int   g_bsum[256];
// W per layer, TRANSPOSED [n][k], bf16 hi/lo, padded rows (136 bf16)
__device__ __align__(16) __nv_bfloat16 g_wbh[2][128 * 136];
__device__ __align__(16) __nv_bfloat16 g_wbl[2][128 * 136];

// ---------------- helpers ----------------
__device__ __forceinline__ void cvt_hi_lo(float a, float b, uint32_t& hi, uint32_t& lo) {
    __nv_bfloat16 ha = __float2bfloat16_rn(a), hb = __float2bfloat16_rn(b);
    float ra = a - __bfloat162float(ha), rb = b - __bfloat162float(hb);
    __nv_bfloat16 la = __float2bfloat16_rn(ra), lb = __float2bfloat16_rn(rb);
    hi = ((uint32_t)(*(unsigned short*)&hb) << 16) | (*(unsigned short*)&ha);
    lo = ((uint32_t)(*(unsigned short*)&lb) << 16) | (*(unsigned short*)&la);
}
__device__ __forceinline__ void mma_bf16(float c[4], const uint32_t a[4], uint32_t b0, uint32_t b1) {
    asm volatile(
        "mma.sync.aligned.m16n8k16.row.col.f32.bf16.bf16.f32 "
        "{%0,%1,%2,%3}, {%4,%5,%6,%7}, {%8,%9}, {%0,%1,%2,%3};"
        : "+f"(c[0]), "+f"(c[1]), "+f"(c[2]), "+f"(c[3])
        : "r"(a[0]), "r"(a[1]), "r"(a[2]), "r"(a[3]), "r"(b0), "r"(b1));
}

// ============================================================================
// Fused prep: blocks [0,128) build W^T bf16 hi/lo images; blocks [128,128+nb)
// init g_deg = 1 (self loop pre-counted); block 128 zeroes scan state.
// ============================================================================
__global__ void prep_kernel(const float* __restrict__ W1, const float* __restrict__ W2, int n) {
    int b = blockIdx.x, t = threadIdx.x;
    if (b < 128) {
        int idx = b * 256 + t;                 // 0..32767
        int layer = idx >> 14;
        int e = idx & 16383;
        int nn = e >> 7, k = e & 127;          // write coalesced in k
        float v = (layer ? W2 : W1)[k * 128 + nn];
        __nv_bfloat16 h = __float2bfloat16_rn(v);
        float r = v - __bfloat162float(h);
        g_wbh[layer][nn * 136 + k] = h;
        g_wbl[layer][nn * 136 + k] = __float2bfloat16_rn(r);
    } else {
        int i = (b - 128) * 256 + t;
        if (i < n) g_deg[i] = 1;               // self loop
        if (b == 128) g_bsum[t] = 0;
    }
}

// ============================================================================
// CSR build
// ============================================================================
__global__ void count_deg_kernel(const int* __restrict__ ei, int E) {
    int i = blockIdx.x * blockDim.x + threadIdx.x;
    if (i < E) atomicAdd(&g_deg[ei[E + i]], 1);
}

__global__ void scan_rowptr_kernel(int n) {
    __shared__ int sh[256];
    __shared__ int red[256];
    int t = threadIdx.x, b = blockIdx.x;
    int i = b * 256 + t;
    int v = (i < n) ? g_deg[i] : 0;
    sh[t] = v;
    __syncthreads();
    for (int o = 1; o < 256; o <<= 1) {
        int u = (t >= o) ? sh[t - o] : 0;
        __syncthreads();
        sh[t] += u;
        __syncthreads();
    }
    if (t == 255) atomicExch(&g_bsum[b], sh[255] + SCAN_FLAG);
    int agg = 0;
    for (int p = t; p < b; p += 256) {
        int val;
        do { val = *(volatile int*)&g_bsum[p]; } while (val < SCAN_FLAG);
        agg += val - SCAN_FLAG;
    }
    red[t] = agg;
    __syncthreads();
    for (int o = 128; o; o >>= 1) {
        if (t < o) red[t] += red[t + o];
        __syncthreads();
    }
    int excl = red[0] + sh[t] - v;
    if (i < n) {
        g_rowptr[i] = excl;
        g_cursor[i] = excl;
        if (i == n - 1) g_rowptr[n] = excl + v;
    }
}

__global__ void scatter_edges_kernel(const int* __restrict__ ei, int E, int n) {
    int i = blockIdx.x * blockDim.x + threadIdx.x;
    if (i < E) {
        int s = ei[i];
        int d = ei[E + i];
        g_csrsrc[atomicAdd(&g_cursor[d], 1)] = s;
    } else if (i < E + n) {
        int v = i - E;
        g_csrsrc[atomicAdd(&g_cursor[v], 1)] = v;   // self loop
    }
}

// ============================================================================
// PERSISTENT bf16-split GEMM + attention, SOFTWARE-PIPELINED (unchanged r14).
// ============================================================================
constexpr uint32_t SMEM_WORDS = 6 * IMG_W + 1024;    // X0h|X0l|X1h|X1l|Bh|Bl + staging
constexpr uint32_t SMEM_BYTES = SMEM_WORDS * 4;      // 212992

__global__ __launch_bounds__(512) void gemm_mma_kernel(
    const float* __restrict__ X,
    const float4* __restrict__ Wbh_g, const float4* __restrict__ Wbl_g,
    const float* __restrict__ atts, const float* __restrict__ attd,
    float* __restrict__ XL, int n)
{
    extern __shared__ uint32_t smu[];
    uint32_t* Xb[2][2];
    Xb[0][0] = smu;
    Xb[0][1] = smu + IMG_W;
    Xb[1][0] = smu + 2 * IMG_W;
    Xb[1][1] = smu + 3 * IMG_W;
    uint32_t* Bh = smu + 4 * IMG_W;
    uint32_t* Bl = smu + 5 * IMG_W;
    float* sh_s = (float*)(smu + 6 * IMG_W);
    float* sh_d = sh_s + 512;

    int tid = threadIdx.x, lane = tid & 31, warp = tid >> 5;
    int gid = lane >> 2, tig = lane & 3;
    int nquad = warp >> 2;
    int rbase = (warp & 3) * 32;

    {
        float4* dh = (float4*)Bh;
        float4* dl = (float4*)Bl;
#pragma unroll
        for (int i = 0; i < 5; i++) {
            int idx = tid + i * 512;
            if (idx < IMG_F4) { dh[idx] = Wbh_g[idx]; dl[idx] = Wbl_g[idx]; }
        }
    }

    float avs[4][2], avd[4][2];
#pragma unroll
    for (int nt = 0; nt < 4; nt++) {
        int col = nquad * 32 + nt * 8 + tig * 2;
        avs[nt][0] = __ldg(atts + col); avs[nt][1] = __ldg(atts + col + 1);
        avd[nt][0] = __ldg(attd + col); avd[nt][1] = __ldg(attd + col + 1);
    }

    const float4* X4 = (const float4*)X;
    int ntiles = (n + 127) >> 7;
    int lr[8], lc[8];
#pragma unroll
    for (int j = 0; j < 8; j++) {
        int idx = tid + j * 512;
        lr[j] = idx >> 5; lc[j] = idx & 31;
    }

    {
        int row0 = blockIdx.x << 7;
#pragma unroll
        for (int j = 0; j < 8; j++) {
            float4 v = make_float4(0.f, 0.f, 0.f, 0.f);
            if (row0 + lr[j] < n) v = X4[(size_t)(row0 + lr[j]) * 32 + lc[j]];
            uint32_t h0, l0, h1, l1;
            cvt_hi_lo(v.x, v.y, h0, l0);
            cvt_hi_lo(v.z, v.w, h1, l1);
            int w = lr[j] * RW + lc[j] * 2;
            *(uint2*)(Xb[0][0] + w) = make_uint2(h0, h1);
            *(uint2*)(Xb[0][1] + w) = make_uint2(l0, l1);
        }
    }
    __syncthreads();

    int buf = 0;
    for (int tile = blockIdx.x; tile < ntiles; tile += gridDim.x, buf ^= 1) {
        int row0 = tile << 7;
        uint32_t* Xh = Xb[buf][0];
        uint32_t* Xl = Xb[buf][1];
        uint32_t* Yh = Xb[buf ^ 1][0];
        uint32_t* Yl = Xb[buf ^ 1][1];
        int nrow0 = (tile + gridDim.x) << 7;
        bool have_next = (tile + gridDim.x) < ntiles;

        float c[2][4][4];
#pragma unroll
        for (int g = 0; g < 2; g++)
#pragma unroll
            for (int nt = 0; nt < 4; nt++)
                c[g][nt][0] = c[g][nt][1] = c[g][nt][2] = c[g][nt][3] = 0.f;

        int aro = (rbase + gid) * RW + tig;
        int bro = (nquad * 32 + gid) * RW + tig;

        float4 pv[4];
        if (have_next) {
#pragma unroll
            for (int j = 0; j < 4; j++) {
                pv[j] = make_float4(0.f, 0.f, 0.f, 0.f);
                if (nrow0 + lr[j] < n) pv[j] = X4[(size_t)(nrow0 + lr[j]) * 32 + lc[j]];
            }
        }
#pragma unroll
        for (int ks = 0; ks < 4; ks++) {
            int kw = ks * 8;
            uint32_t ah[2][4], al[2][4];
#pragma unroll
            for (int g = 0; g < 2; g++) {
                int o = aro + g * (16 * RW) + kw;
                ah[g][0] = Xh[o];              al[g][0] = Xl[o];
                ah[g][1] = Xh[o + 8 * RW];     al[g][1] = Xl[o + 8 * RW];
                ah[g][2] = Xh[o + 4];          al[g][2] = Xl[o + 4];
                ah[g][3] = Xh[o + 8 * RW + 4]; al[g][3] = Xl[o + 8 * RW + 4];
            }
#pragma unroll
            for (int nt = 0; nt < 4; nt++) {
                int o = bro + nt * (8 * RW) + kw;
                uint32_t bh0 = Bh[o], bh1 = Bh[o + 4];
                uint32_t bl0 = Bl[o], bl1 = Bl[o + 4];
                mma_bf16(c[0][nt], ah[0], bh0, bh1);
                mma_bf16(c[0][nt], ah[0], bl0, bl1);
                mma_bf16(c[0][nt], al[0], bh0, bh1);
                mma_bf16(c[1][nt], ah[1], bh0, bh1);
                mma_bf16(c[1][nt], ah[1], bl0, bl1);
                mma_bf16(c[1][nt], al[1], bh0, bh1);
            }
        }
        if (have_next) {
#pragma unroll
            for (int j = 0; j < 4; j++) {
                uint32_t h0, l0, h1, l1;
                cvt_hi_lo(pv[j].x, pv[j].y, h0, l0);
                cvt_hi_lo(pv[j].z, pv[j].w, h1, l1);
                int w = lr[j] * RW + lc[j] * 2;
                *(uint2*)(Yh + w) = make_uint2(h0, h1);
                *(uint2*)(Yl + w) = make_uint2(l0, l1);
            }
#pragma unroll
            for (int j = 0; j < 4; j++) {
                pv[j] = make_float4(0.f, 0.f, 0.f, 0.f);
                if (nrow0 + lr[j + 4] < n) pv[j] = X4[(size_t)(nrow0 + lr[j + 4]) * 32 + lc[j + 4]];
            }
        }
#pragma unroll
        for (int ks = 4; ks < 8; ks++) {
            int kw = ks * 8;
            uint32_t ah[2][4], al[2][4];
#pragma unroll
            for (int g = 0; g < 2; g++) {
                int o = aro + g * (16 * RW) + kw;
                ah[g][0] = Xh[o];              al[g][0] = Xl[o];
                ah[g][1] = Xh[o + 8 * RW];     al[g][1] = Xl[o + 8 * RW];
                ah[g][2] = Xh[o + 4];          al[g][2] = Xl[o + 4];
                ah[g][3] = Xh[o + 8 * RW + 4]; al[g][3] = Xl[o + 8 * RW + 4];
            }
#pragma unroll
            for (int nt = 0; nt < 4; nt++) {
                int o = bro + nt * (8 * RW) + kw;
                uint32_t bh0 = Bh[o], bh1 = Bh[o + 4];
                uint32_t bl0 = Bl[o], bl1 = Bl[o + 4];
                mma_bf16(c[0][nt], ah[0], bh0, bh1);
                mma_bf16(c[0][nt], ah[0], bl0, bl1);
                mma_bf16(c[0][nt], al[0], bh0, bh1);
                mma_bf16(c[1][nt], ah[1], bh0, bh1);
                mma_bf16(c[1][nt], ah[1], bl0, bl1);
                mma_bf16(c[1][nt], al[1], bh0, bh1);
            }
        }
        if (have_next) {
#pragma unroll
            for (int j = 0; j < 4; j++) {
                uint32_t h0, l0, h1, l1;
                cvt_hi_lo(pv[j].x, pv[j].y, h0, l0);
                cvt_hi_lo(pv[j].z, pv[j].w, h1, l1);
                int w = lr[j + 4] * RW + lc[j + 4] * 2;
                *(uint2*)(Yh + w) = make_uint2(h0, h1);
                *(uint2*)(Yl + w) = make_uint2(l0, l1);
            }
        }

#pragma unroll
        for (int g = 0; g < 2; g++) {
            float ps0 = 0.f, pd0 = 0.f, ps1 = 0.f, pd1 = 0.f;
#pragma unroll
            for (int nt = 0; nt < 4; nt++) {
                ps0 = fmaf(c[g][nt][0], avs[nt][0], fmaf(c[g][nt][1], avs[nt][1], ps0));
                pd0 = fmaf(c[g][nt][0], avd[nt][0], fmaf(c[g][nt][1], avd[nt][1], pd0));
                ps1 = fmaf(c[g][nt][2], avs[nt][0], fmaf(c[g][nt][3], avs[nt][1], ps1));
                pd1 = fmaf(c[g][nt][2], avd[nt][0], fmaf(c[g][nt][3], avd[nt][1], pd1));
            }
#pragma unroll
            for (int o = 1; o <= 2; o <<= 1) {
                ps0 += __shfl_xor_sync(0xffffffffu, ps0, o);
                pd0 += __shfl_xor_sync(0xffffffffu, pd0, o);
                ps1 += __shfl_xor_sync(0xffffffffu, ps1, o);
                pd1 += __shfl_xor_sync(0xffffffffu, pd1, o);
            }
            int rloc = rbase + g * 16 + gid;
            if (tig == 0) {
                sh_s[nquad * 128 + rloc]     = ps0;
                sh_d[nquad * 128 + rloc]     = pd0;
                sh_s[nquad * 128 + rloc + 8] = ps1;
                sh_d[nquad * 128 + rloc + 8] = pd1;
            }
            int r0 = row0 + rloc;
            int r1 = r0 + 8;
            if (r0 < n) {
                float* dst = XL + (size_t)r0 * 128 + nquad * 32 + tig * 2;
#pragma unroll
                for (int nt = 0; nt < 4; nt++)
                    *(float2*)(dst + nt * 8) = make_float2(c[g][nt][0], c[g][nt][1]);
            }
            if (r1 < n) {
                float* dst = XL + (size_t)r1 * 128 + nquad * 32 + tig * 2;
#pragma unroll
                for (int nt = 0; nt < 4; nt++)
                    *(float2*)(dst + nt * 8) = make_float2(c[g][nt][2], c[g][nt][3]);
            }
        }

        __syncthreads();
        if (tid < 128) {
            int r = row0 + tid;
            if (r < n) {
                g_as[r] = (sh_s[tid] + sh_s[128 + tid]) + (sh_s[256 + tid] + sh_s[384 + tid]);
                g_ad[r] = (sh_d[tid] + sh_d[128 + tid]) + (sh_d[256 + tid] + sh_d[384 + tid]);
            }
        }
    }
}

// ============================================================================
// Aggregation (softmax weight inlined): one warp per dst node.
// Index stream vectorized: csrsrc loaded as int4 (1 LDG per 4 edges).
//   w_e = exp(leakyrelu(a_s[src_e] + a_d[v]))
//   out[v] = relu( (sum_e w_e * XL[src_e]) / (sum_e w_e + 1e-16) + b )
// ============================================================================
__device__ __forceinline__ float edge_w(float as_v, float adv) {
    float t = as_v + adv;
    t = t > 0.f ? t : 0.2f * t;
    return __expf(t);
}

__global__ __launch_bounds__(256) void aggregate_kernel(
    const float* __restrict__ XL, const float* __restrict__ bias,
    float* __restrict__ OUT, int n)
{
    int wid = blockIdx.x * 8 + (threadIdx.x >> 5);
    int lane = threadIdx.x & 31;
    if (wid >= n) return;

    int beg = g_rowptr[wid];
    int end = g_rowptr[wid + 1];
    float adv = g_ad[wid];
    float4 acc = make_float4(0.f, 0.f, 0.f, 0.f);
    float z = 0.f;
    const float4* XL4 = (const float4*)XL;

    int j = beg;
    // peel to 4-aligned offset (g_csrsrc is 16B-aligned)
    int jal = (beg + 3) & ~3;
    for (; j < end && j < jal; j++) {
        int s = g_csrsrc[j];
        float w = edge_w(g_as[s], adv);
        float4 xv = XL4[(size_t)s * 32 + lane];
        acc.x = fmaf(w, xv.x, acc.x); acc.y = fmaf(w, xv.y, acc.y);
        acc.z = fmaf(w, xv.z, acc.z); acc.w = fmaf(w, xv.w, acc.w);
        z += w;
    }
    for (; j + 4 <= end; j += 4) {
        int4 s4 = *(const int4*)&g_csrsrc[j];   // 1 LDG for 4 indices
        float w0 = edge_w(g_as[s4.x], adv);
        float w1 = edge_w(g_as[s4.y], adv);
        float w2 = edge_w(g_as[s4.z], adv);
        float w3 = edge_w(g_as[s4.w], adv);
        float4 x0 = XL4[(size_t)s4.x * 32 + lane];
        float4 x1 = XL4[(size_t)s4.y * 32 + lane];
        float4 x2 = XL4[(size_t)s4.z * 32 + lane];
        float4 x3 = XL4[(size_t)s4.w * 32 + lane];
        acc.x = fmaf(w0, x0.x, acc.x); acc.y = fmaf(w0, x0.y, acc.y);
        acc.z = fmaf(w0, x0.z, acc.z); acc.w = fmaf(w0, x0.w, acc.w);
        acc.x = fmaf(w1, x1.x, acc.x); acc.y = fmaf(w1, x1.y, acc.y);
        acc.z = fmaf(w1, x1.z, acc.z); acc.w = fmaf(w1, x1.w, acc.w);
        acc.x = fmaf(w2, x2.x, acc.x); acc.y = fmaf(w2, x2.y, acc.y);
        acc.z = fmaf(w2, x2.z, acc.z); acc.w = fmaf(w2, x2.w, acc.w);
        acc.x = fmaf(w3, x3.x, acc.x); acc.y = fmaf(w3, x3.y, acc.y);
        acc.z = fmaf(w3, x3.z, acc.z); acc.w = fmaf(w3, x3.w, acc.w);
        z += (w0 + w1) + (w2 + w3);
    }
    for (; j < end; j++) {
        int s = g_csrsrc[j];
        float w = edge_w(g_as[s], adv);
        float4 xv = XL4[(size_t)s * 32 + lane];
        acc.x = fmaf(w, xv.x, acc.x); acc.y = fmaf(w, xv.y, acc.y);
        acc.z = fmaf(w, xv.z, acc.z); acc.w = fmaf(w, xv.w, acc.w);
        z += w;
    }

    float inv = 1.f / (z + 1e-16f);
    float4 bv = ((const float4*)bias)[lane];
    float4 o;
    o.x = fmaxf(fmaf(acc.x, inv, bv.x), 0.f);
    o.y = fmaxf(fmaf(acc.y, inv, bv.y), 0.f);
    o.z = fmaxf(fmaf(acc.z, inv, bv.z), 0.f);
    o.w = fmaxf(fmaf(acc.w, inv, bv.w), 0.f);
    ((float4*)OUT)[(size_t)wid * 32 + lane] = o;
}

// ============================================================================
// Launch (8 kernels). gemm1 kept at slot 4 (the profiled slot).
// ============================================================================
extern "C" void kernel_launch(void* const* d_in, const int* in_sizes, int n_in,
                              void* d_out, int out_size)
{
    const float* x   = (const float*)d_in[0];
    const int*   ei  = (const int*)d_in[1];
    const float* W1  = (const float*)d_in[2];
    const float* as1 = (const float*)d_in[3];
    const float* ad1 = (const float*)d_in[4];
    const float* b1  = (const float*)d_in[5];
    const float* W2  = (const float*)d_in[6];
    const float* as2 = (const float*)d_in[7];
    const float* ad2 = (const float*)d_in[8];
    const float* b2  = (const float*)d_in[9];

    int n = in_sizes[0] / DDIM;   // 50000
    int E = in_sizes[1] / 2;      // 800000
    int ee = E + n;
    float* out = (float*)d_out;

    void *xl_p, *h_p, *wh_p, *wl_p;
    cudaGetSymbolAddress(&xl_p, g_xl);
    cudaGetSymbolAddress(&h_p,  g_h);
    cudaGetSymbolAddress(&wh_p, g_wbh);
    cudaGetSymbolAddress(&wl_p, g_wbl);
    float* xl = (float*)xl_p;
    float* h  = (float*)h_p;
    const __nv_bfloat16* wbh = (const __nv_bfloat16*)wh_p;
    const __nv_bfloat16* wbl = (const __nv_bfloat16*)wl_p;

    cudaFuncSetAttribute(gemm_mma_kernel, cudaFuncAttributeMaxDynamicSharedMemorySize, SMEM_BYTES);

    int nb = (n + 255) / 256;     // 196

    // --- prep & CSR build (gemm1 at slot 4 for profiling) ---
    prep_kernel<<<128 + nb, 256>>>(W1, W2, n);
    count_deg_kernel<<<(E + 255) / 256, 256>>>(ei, E);
    scan_rowptr_kernel<<<nb, 256>>>(n);
    gemm_mma_kernel<<<GEMM_GRID, 512, SMEM_BYTES>>>(
        x, (const float4*)wbh, (const float4*)wbl, as1, ad1, xl, n);
    scatter_edges_kernel<<<(ee + 255) / 256, 256>>>(ei, E, n);

    // --- Layer 1 aggregate ---
    aggregate_kernel<<<(n + 7) / 8, 256>>>(xl, b1, h, n);

    // --- Layer 2 ---
    gemm_mma_kernel<<<GEMM_GRID, 512, SMEM_BYTES>>>(
        h, (const float4*)(wbh + 128 * 136), (const float4*)(wbl + 128 * 136),
        as2, ad2, xl, n);
    aggregate_kernel<<<(n + 7) / 8, 256>>>(xl, b2, out, n);
}